// round 13
// baseline (speedup 1.0000x reference)
#include <cuda_runtime.h>
#include <cuda_bf16.h>
#include <math.h>
#include <stdint.h>

// ---------------------------------------------------------------------------
// Problem constants
// ---------------------------------------------------------------------------
#define BATCH   8192
#define IN_DIM  4096
#define OUT_DIM 2048
#define DEPTH   9
#define RSTEPS  27
#define WIN     55
#define CENTER  27

// Shared GEMM geometry: 128x64 CTA tile, BK=64, 2-stage ring, 256 threads
#define BM 128
#define BN 64
#define BK 64
#define NKT (IN_DIM / BK)            // 64

// bf16-hh kernel stage: Ahi 16K | Bhi 8K
#define H_AHI 0
#define H_BHI 16384
#define H_STAGE 24576
#define H_SMEM (2 * H_STAGE)         // 49152

// int8 kernel stage: A8H 8K | A8L 8K | B8L 4K | B8H 4K
#define I_A8H 0
#define I_A8L 8192
#define I_B8L 16384
#define I_B8H 20480
#define I_STAGE 24576
#define I_SMEM (2 * I_STAGE)         // 49152

// ---------------------------------------------------------------------------
// Device-global scratch (static: no runtime allocation)
// ---------------------------------------------------------------------------
__device__ float         g_pb[OUT_DIM];
__device__ float         g_rfac[BATCH];     // s_xh(m) = rmax*1.02/127
__device__ float         g_cfl[OUT_DIM];    // s_wl(n) = cmax*1.02/(127*256)
__device__ float         g_cmax[OUT_DIM];
__device__ __nv_bfloat16 g_xhi[(size_t)BATCH * IN_DIM];      // 64 MB
__device__ __nv_bfloat16 g_wThi[(size_t)OUT_DIM * IN_DIM];   // 16 MB (W^T hi)
__device__ int8_t        g_xh8[(size_t)BATCH * IN_DIM];      // 32 MB
__device__ int8_t        g_xl8[(size_t)BATCH * IN_DIM];      // 32 MB
__device__ int8_t        g_w8hT[(size_t)OUT_DIM * IN_DIM];   // 8 MB
__device__ int8_t        g_w8lT[(size_t)OUT_DIM * IN_DIM];   // 8 MB
__device__ float         g_cp[(size_t)BATCH * OUT_DIM];      // 64 MB cross partial

// ---------------------------------------------------------------------------
// PTX helpers (base sm_103 ISA only: cp.async / ldmatrix / mma.sync)
// ---------------------------------------------------------------------------
__device__ __forceinline__ uint32_t smem_u32(const void* p) {
    uint32_t a;
    asm("{ .reg .u64 t; cvta.to.shared.u64 t, %1; cvt.u32.u64 %0, t; }"
        : "=r"(a) : "l"(p));
    return a;
}
__device__ __forceinline__ void cpasync16(uint32_t dst, const void* src) {
    asm volatile("cp.async.cg.shared.global [%0], [%1], 16;"
                 :: "r"(dst), "l"(src));
}
#define CP_COMMIT() asm volatile("cp.async.commit_group;" ::: "memory")
#define CP_WAIT0()  asm volatile("cp.async.wait_group 0;"  ::: "memory")

#define LDSM_X4(d, a) \
    asm volatile("ldmatrix.sync.aligned.m8n8.x4.shared.b16 {%0,%1,%2,%3}, [%4];" \
        : "=r"((d)[0]), "=r"((d)[1]), "=r"((d)[2]), "=r"((d)[3]) : "r"(a))
// 4 separate destinations (for B ni-pair destructuring)
#define LDSM_X4D(d0, d1, d2, d3, a) \
    asm volatile("ldmatrix.sync.aligned.m8n8.x4.shared.b16 {%0,%1,%2,%3}, [%4];" \
        : "=r"(d0), "=r"(d1), "=r"(d2), "=r"(d3) : "r"(a))

#define MMA16816(c, a, b) \
    asm volatile("mma.sync.aligned.m16n8k16.row.col.f32.bf16.bf16.f32 " \
        "{%0,%1,%2,%3}, {%4,%5,%6,%7}, {%8,%9}, {%0,%1,%2,%3};" \
        : "+f"((c)[0]), "+f"((c)[1]), "+f"((c)[2]), "+f"((c)[3]) \
        : "r"((a)[0]), "r"((a)[1]), "r"((a)[2]), "r"((a)[3]), \
          "r"((b)[0]), "r"((b)[1]))

#define MMA_I8(c, a, b) \
    asm volatile("mma.sync.aligned.m16n8k32.row.col.s32.s8.s8.s32 " \
        "{%0,%1,%2,%3}, {%4,%5,%6,%7}, {%8,%9}, {%0,%1,%2,%3};" \
        : "+r"((c)[0]), "+r"((c)[1]), "+r"((c)[2]), "+r"((c)[3]) \
        : "r"((a)[0]), "r"((a)[1]), "r"((a)[2]), "r"((a)[3]), \
          "r"((b)[0]), "r"((b)[1]))

// SW128 swizzle, 128B physical rows (bf16 tiles: 64 bf16 = 128B per row)
__device__ __forceinline__ uint32_t swz128(uint32_t base, int row, int cc) {
    return base + row * 128 + (((cc) ^ (row & 7)) << 4);
}
// SW swizzle, 64B logical rows packed 2-per-128B (int8 tiles: 64B per row)
__device__ __forceinline__ uint32_t swz64(uint32_t base, int row, int cc) {
    int p  = row >> 1;
    int c8 = ((row & 1) << 2) | cc;
    return base + p * 128 + ((c8 ^ (p & 7)) << 4);
}

// ---------------------------------------------------------------------------
// Prep kernel A: W column-max (blocks 0..7) + universal probs (blocks 8..15)
// ---------------------------------------------------------------------------
__global__ __launch_bounds__(256)
void prepA_kernel(const float* __restrict__ W,
                  const float* __restrict__ uw,
                  const float* __restrict__ bias) {
    const int b = blockIdx.x, tid = threadIdx.x;
    if (b < 8) {
        const int n = b * 256 + tid;
        float m = 1e-6f;
        for (int k = 0; k < IN_DIM; k++)
            m = fmaxf(m, fabsf(W[(size_t)k * OUT_DIM + n]));
        g_cmax[n] = m;
        g_cfl[n]  = m * 1.02f / (127.0f * 256.0f);
    } else {
        const int o = (b - 8) * 256 + tid;
        float w[WIN];
#pragma unroll
        for (int j = 0; j < WIN; j++) w[j] = 0.015625f;   // 1/sqrt(4096)
#pragma unroll
        for (int s = 0; s < RSTEPS; s++) {
            const int d = s / 3, g = s % 3;
            float ang = uw[(size_t)d * IN_DIM * OUT_DIM + (size_t)o * OUT_DIM + g];
            float sn, cs;
            sincosf(ang, &sn, &cs);
            float nw[WIN];
            nw[0] = w[0]; nw[WIN - 1] = w[WIN - 1];
#pragma unroll
            for (int j = 1; j < WIN - 1; j++)
                nw[j] = cs * w[j] - sn * w[j + 1] + sn * w[j - 1];
#pragma unroll
            for (int j = 0; j < WIN; j++) w[j] = nw[j];
        }
        g_pb[o] = w[CENTER] * w[CENTER] + bias[o];
    }
}

// ---------------------------------------------------------------------------
// Prep kernel B: per-row split of x. One block per row: pass 1 row-max
// (row = 16KB, stays in L1 for pass 2), pass 2 quantize hi(bf16)/hi8/lo8.
// ---------------------------------------------------------------------------
__global__ __launch_bounds__(256)
void prepX_kernel(const float* __restrict__ x) {
    __shared__ float red[256];
    const int m   = blockIdx.x;
    const int tid = threadIdx.x;
    const float* row = x + (size_t)m * IN_DIM;

    float mx = 0.0f;
#pragma unroll
    for (int i = 0; i < 4; i++) {
        float4 v = *(const float4*)(row + (tid + 256 * i) * 4);
        mx = fmaxf(mx, fmaxf(fmaxf(fabsf(v.x), fabsf(v.y)),
                             fmaxf(fabsf(v.z), fabsf(v.w))));
    }
    red[tid] = mx;
    __syncthreads();
    for (int s = 128; s > 0; s >>= 1) {
        if (tid < s) red[tid] = fmaxf(red[tid], red[tid + s]);
        __syncthreads();
    }
    const float rmax = fmaxf(red[0], 1e-6f);
    const float qh   = 127.0f / (rmax * 1.02f);
    const float ql   = qh * 256.0f;
    if (tid == 0) g_rfac[m] = rmax * 1.02f / 127.0f;

#pragma unroll
    for (int i = 0; i < 4; i++) {
        const size_t idx = (size_t)m * IN_DIM + (tid + 256 * i) * 4;
        float4 v = *(const float4*)(row + (tid + 256 * i) * 4);
        __nv_bfloat16 h0 = __float2bfloat16(v.x);
        __nv_bfloat16 h1 = __float2bfloat16(v.y);
        __nv_bfloat16 h2 = __float2bfloat16(v.z);
        __nv_bfloat16 h3 = __float2bfloat16(v.w);
        float f0 = __bfloat162float(h0), f1 = __bfloat162float(h1);
        float f2 = __bfloat162float(h2), f3 = __bfloat162float(h3);
        __nv_bfloat162* ph = (__nv_bfloat162*)(g_xhi + idx);
        ph[0] = __nv_bfloat162(h0, h1);
        ph[1] = __nv_bfloat162(h2, h3);
        int q0 = __float2int_rn(f0 * qh), q1 = __float2int_rn(f1 * qh);
        int q2 = __float2int_rn(f2 * qh), q3 = __float2int_rn(f3 * qh);
        *(uint32_t*)(g_xh8 + idx) = (uint32_t)(q0 & 255) | ((uint32_t)(q1 & 255) << 8) |
                                    ((uint32_t)(q2 & 255) << 16) | ((uint32_t)(q3 & 255) << 24);
        int l0 = __float2int_rn((v.x - f0) * ql), l1 = __float2int_rn((v.y - f1) * ql);
        int l2 = __float2int_rn((v.z - f2) * ql), l3 = __float2int_rn((v.w - f3) * ql);
        *(uint32_t*)(g_xl8 + idx) = (uint32_t)(l0 & 255) | ((uint32_t)(l1 & 255) << 8) |
                                    ((uint32_t)(l2 & 255) << 16) | ((uint32_t)(l3 & 255) << 24);
    }
}

// ---------------------------------------------------------------------------
// Prep kernel C: transpose + split W -> wThi (bf16), w8hT, w8lT (int8, per-col
// scales from g_cmax). Runs AFTER prepA.
// ---------------------------------------------------------------------------
__global__ __launch_bounds__(256)
void prepW_kernel(const float* __restrict__ W) {
    __shared__ float t[32][33];
    const int n0 = blockIdx.x * 32, k0 = blockIdx.y * 32;
    const int tx = threadIdx.x & 31, ty = threadIdx.x >> 5;   // 32 x 8
#pragma unroll
    for (int i = 0; i < 32; i += 8)
        t[ty + i][tx] = W[(size_t)(k0 + ty + i) * OUT_DIM + n0 + tx];
    __syncthreads();
#pragma unroll
    for (int i = 0; i < 32; i += 8) {
        const int n = n0 + ty + i;
        const float cmax = g_cmax[n];
        const float qwh  = 127.0f / (cmax * 1.02f);
        const float qwl  = qwh * 256.0f;
        float v = t[tx][ty + i];
        __nv_bfloat16 h = __float2bfloat16(v);
        float hf = __bfloat162float(h);
        size_t o = (size_t)n * IN_DIM + k0 + tx;
        g_wThi[o] = h;
        g_w8hT[o] = (int8_t)__float2int_rn(hf * qwh);
        g_w8lT[o] = (int8_t)__float2int_rn((v - hf) * qwl);
    }
}

// ---------------------------------------------------------------------------
// Kernel: int8 cross-term GEMM. Cp = s_xh(m)*s_wl(n) * (xh8·w8l^T + xl8·w8h^T)
// (scales matched by the 2^8 hi/lo ratio so both products share ONE s32 acc).
// R12 ring discipline: 2-stage, wait0+barrier at top, mid-iteration refill.
// ---------------------------------------------------------------------------
__global__ __launch_bounds__(256, 2)
void gemm_i8_kernel(void) {
    extern __shared__ char smem[];
    const uint32_t sb = smem_u32(smem);

    const int tid  = threadIdx.x;
    const int lane = tid & 31;
    const int wid  = tid >> 5;
    const int wm   = wid >> 1;          // 0..3
    const int wn   = wid & 1;           // 0..1
    const int gid  = lane >> 2;
    const int tg   = lane & 3;
    const int bm   = blockIdx.y * BM;
    const int bn   = blockIdx.x * BN;

    // Loads: A8 tiles 128x64B -> 512 chunks (2/thread); B8 64x64B -> 256 (1/thread)
    const int rA = tid >> 2;            // 0..63
    const int cc = tid & 3;

    const int8_t* pAh = g_xh8  + (size_t)(bm + rA) * IN_DIM + cc * 16;
    const int8_t* pAl = g_xl8  + (size_t)(bm + rA) * IN_DIM + cc * 16;
    const int8_t* pBl = g_w8lT + (size_t)(bn + rA) * IN_DIM + cc * 16;
    const int8_t* pBh = g_w8hT + (size_t)(bn + rA) * IN_DIM + cc * 16;

    const uint32_t dAh = swz64(I_A8H, rA, cc);
    const uint32_t dAl = swz64(I_A8L, rA, cc);
    const uint32_t dBl = swz64(I_B8L, rA, cc);
    const uint32_t dBh = swz64(I_B8H, rA, cc);

#define I8_ISSUE(stg, kc)                                                    \
    do {                                                                     \
        uint32_t s_ = sb + (stg) * I_STAGE;                                  \
        size_t ko_ = (size_t)(kc) * BK;                                      \
        cpasync16(s_ + dAh,        pAh + ko_);                               \
        cpasync16(s_ + dAh + 4096, pAh + ko_ + (size_t)64 * IN_DIM);         \
        cpasync16(s_ + dAl,        pAl + ko_);                               \
        cpasync16(s_ + dAl + 4096, pAl + ko_ + (size_t)64 * IN_DIM);         \
        cpasync16(s_ + dBl,        pBl + ko_);                               \
        cpasync16(s_ + dBh,        pBh + ko_);                               \
    } while (0)

    int acc[2][4][4];
#pragma unroll
    for (int i = 0; i < 2; i++)
#pragma unroll
        for (int j = 0; j < 4; j++)
#pragma unroll
            for (int q = 0; q < 4; q++) acc[i][j][q] = 0;

    // ldmatrix lane mapping for s8 m16n8k32 fragments (b16 trick):
    // 4 groups of 8 lanes -> (rows 0-7/8-15) x (16B half 0/1) of a 32B window
    const int frow = (lane & 7) + (((lane >> 3) & 1) << 3);
    const int fsel = lane >> 4;

    uint32_t oA8[2][2], oB8[2][2];      // [g][mi] / [g][nj]
#pragma unroll
    for (int g = 0; g < 2; g++) {
#pragma unroll
        for (int mi = 0; mi < 2; mi++)
            oA8[g][mi] = swz64(0, wm * 32 + mi * 16 + frow, g * 2 + fsel);
#pragma unroll
        for (int nj = 0; nj < 2; nj++)
            oB8[g][nj] = swz64(0, wn * 32 + nj * 16 + frow, g * 2 + fsel);
    }

    uint32_t a8h[2][4], a8l[2][4], b8l[4][2], b8h[4][2];

#define I8_LOAD_AH(SB, G) do {                                               \
        LDSM_X4(a8h[0], (SB) + I_A8H + oA8[G][0]);                           \
        LDSM_X4(a8h[1], (SB) + I_A8H + oA8[G][1]); } while (0)
#define I8_LOAD_AL(SB, G) do {                                               \
        LDSM_X4(a8l[0], (SB) + I_A8L + oA8[G][0]);                           \
        LDSM_X4(a8l[1], (SB) + I_A8L + oA8[G][1]); } while (0)
#define I8_LOAD_BL(SB, G) do {                                               \
        LDSM_X4D(b8l[0][0], b8l[1][0], b8l[0][1], b8l[1][1], (SB) + I_B8L + oB8[G][0]); \
        LDSM_X4D(b8l[2][0], b8l[3][0], b8l[2][1], b8l[3][1], (SB) + I_B8L + oB8[G][1]); } while (0)
#define I8_LOAD_BH(SB, G) do {                                               \
        LDSM_X4D(b8h[0][0], b8h[1][0], b8h[0][1], b8h[1][1], (SB) + I_B8H + oB8[G][0]); \
        LDSM_X4D(b8h[2][0], b8h[3][0], b8h[2][1], b8h[3][1], (SB) + I_B8H + oB8[G][1]); } while (0)

#define I8_MMA(A, B)                                                         \
    do {                                                                     \
        _Pragma("unroll")                                                    \
        for (int mi = 0; mi < 2; mi++)                                       \
            _Pragma("unroll")                                                \
            for (int ni = 0; ni < 4; ni++)                                   \
                MMA_I8(acc[mi][ni], A[mi], B[ni]);                           \
    } while (0)

    I8_ISSUE(0, 0);
    CP_COMMIT();

#pragma unroll 1
    for (int kt = 0; kt < NKT; kt++) {
        CP_WAIT0();
        __syncthreads();
        const uint32_t s_ = sb + (kt & 1) * I_STAGE;

        // group 0 loads
        I8_LOAD_AH(s_, 0); I8_LOAD_BL(s_, 0);
        I8_LOAD_AL(s_, 0); I8_LOAD_BH(s_, 0);
        I8_MMA(a8h, b8l);                       // g0 hi*lo

        if (kt + 1 < NKT) {
            I8_ISSUE((kt + 1) & 1, kt + 1);
            CP_COMMIT();
        }

        I8_LOAD_AH(s_, 1); I8_LOAD_BL(s_, 1);   // overwrite a8h/b8l (done)
        I8_MMA(a8l, b8h);                       // g0 lo*hi
        I8_LOAD_AL(s_, 1); I8_LOAD_BH(s_, 1);
        I8_MMA(a8h, b8l);                       // g1 hi*lo
        I8_MMA(a8l, b8h);                       // g1 lo*hi
    }

    // Epilogue: Cp = acc * rfac(m) * cfl(n)
    float rf[2][2];
#pragma unroll
    for (int mi = 0; mi < 2; mi++) {
        rf[mi][0] = g_rfac[bm + wm * 32 + mi * 16 + gid];
        rf[mi][1] = g_rfac[bm + wm * 32 + mi * 16 + gid + 8];
    }
    float cf[4][2];
#pragma unroll
    for (int ni = 0; ni < 4; ni++) {
        const int col = bn + wn * 32 + ni * 8 + tg * 2;
        cf[ni][0] = g_cfl[col];
        cf[ni][1] = g_cfl[col + 1];
    }
#pragma unroll
    for (int mi = 0; mi < 2; mi++) {
        const int r = bm + wm * 32 + mi * 16 + gid;
#pragma unroll
        for (int ni = 0; ni < 4; ni++) {
            const int col = bn + wn * 32 + ni * 8 + tg * 2;
            float2 v0, v1;
            v0.x = (float)acc[mi][ni][0] * rf[mi][0] * cf[ni][0];
            v0.y = (float)acc[mi][ni][1] * rf[mi][0] * cf[ni][1];
            v1.x = (float)acc[mi][ni][2] * rf[mi][1] * cf[ni][0];
            v1.y = (float)acc[mi][ni][3] * rf[mi][1] * cf[ni][1];
            *(float2*)(g_cp + (size_t)r * OUT_DIM + col)       = v0;
            *(float2*)(g_cp + (size_t)(r + 8) * OUT_DIM + col) = v1;
        }
    }
}

// ---------------------------------------------------------------------------
// Kernel: bf16 hi*hi GEMM + epilogue combine: out = tanh(acc + Cp + pb).
// R12 pipeline minus all lo machinery (32 MMAs/chunk).
// ---------------------------------------------------------------------------
__global__ __launch_bounds__(256, 2)
void gemm_hh_kernel(float* __restrict__ out) {
    extern __shared__ char smem[];
    const uint32_t sb = smem_u32(smem);

    const int tid  = threadIdx.x;
    const int lane = tid & 31;
    const int wid  = tid >> 5;
    const int wm   = wid >> 1;
    const int wn   = wid & 1;
    const int gid  = lane >> 2;
    const int tg   = lane & 3;
    const int bm   = blockIdx.y * BM;
    const int bn   = blockIdx.x * BN;

    // A 128x128B -> 1024 chunks (4/thread); B 64x128B -> 512 (2/thread)
    const int r0 = tid >> 3;
    const int cA = tid & 7;

    const __nv_bfloat16* pA = g_xhi  + (size_t)(bm + r0) * IN_DIM + cA * 8;
    const __nv_bfloat16* pB = g_wThi + (size_t)(bn + r0) * IN_DIM + cA * 8;
    const uint32_t dA = swz128(H_AHI, r0, cA);
    const uint32_t dB = swz128(H_BHI, r0, cA);

#define HH_ISSUE(stg, kc)                                                    \
    do {                                                                     \
        uint32_t s_ = sb + (stg) * H_STAGE;                                  \
        size_t ko_ = (size_t)(kc) * BK;                                      \
        _Pragma("unroll")                                                    \
        for (int i = 0; i < 4; i++)                                          \
            cpasync16(s_ + dA + i * 4096, pA + ko_ + (size_t)i * 32 * IN_DIM); \
        _Pragma("unroll")                                                    \
        for (int i = 0; i < 2; i++)                                          \
            cpasync16(s_ + dB + i * 4096, pB + ko_ + (size_t)i * 32 * IN_DIM); \
    } while (0)

    float acc[2][4][4];
#pragma unroll
    for (int i = 0; i < 2; i++)
#pragma unroll
        for (int j = 0; j < 4; j++)
#pragma unroll
            for (int q = 0; q < 4; q++) acc[i][j][q] = 0.0f;

    const int a_rl = lane & 15;
    const int a_ch = lane >> 4;
    const int b4_row = ((lane >> 4) << 3) + (lane & 7);
    const int b4_c   = (lane >> 3) & 1;

    uint32_t oA[4][2], oB[4][2];
#pragma unroll
    for (int ks = 0; ks < 4; ks++) {
#pragma unroll
        for (int mi = 0; mi < 2; mi++)
            oA[ks][mi] = swz128(0, wm * 32 + mi * 16 + a_rl, ks * 2 + a_ch);
#pragma unroll
        for (int nj = 0; nj < 2; nj++)
            oB[ks][nj] = swz128(0, wn * 32 + nj * 16 + b4_row, ks * 2 + b4_c);
    }

    uint32_t ah0[2][4], ah1[2][4], bh0[4][2], bh1[4][2];

#define HH_LOAD(AH, BH, SB, KS) do {                                         \
        LDSM_X4(AH[0],     (SB) + H_AHI + oA[KS][0]);                        \
        LDSM_X4(AH[1],     (SB) + H_AHI + oA[KS][1]);                        \
        LDSM_X4(&BH[0][0], (SB) + H_BHI + oB[KS][0]);                        \
        LDSM_X4(&BH[2][0], (SB) + H_BHI + oB[KS][1]); } while (0)

#define HH_MMA(AH, BH)                                                       \
    do {                                                                     \
        _Pragma("unroll")                                                    \
        for (int mi = 0; mi < 2; mi++)                                       \
            _Pragma("unroll")                                                \
            for (int ni = 0; ni < 4; ni++)                                   \
                MMA16816(acc[mi][ni], AH[mi], BH[ni]);                       \
    } while (0)

    HH_ISSUE(0, 0);
    CP_COMMIT();

#pragma unroll 1
    for (int kt = 0; kt < NKT; kt++) {
        CP_WAIT0();
        __syncthreads();
        const uint32_t s_ = sb + (kt & 1) * H_STAGE;

        HH_LOAD(ah0, bh0, s_, 0);
        HH_LOAD(ah1, bh1, s_, 1);
        HH_MMA(ah0, bh0);
        if (kt + 1 < NKT) {
            HH_ISSUE((kt + 1) & 1, kt + 1);
            CP_COMMIT();
        }
        HH_LOAD(ah0, bh0, s_, 2);
        HH_MMA(ah1, bh1);
        HH_LOAD(ah1, bh1, s_, 3);
        HH_MMA(ah0, bh0);
        HH_MMA(ah1, bh1);
    }

    // Epilogue: + Cp + pb, tanh, store
    float pbv[4][2];
#pragma unroll
    for (int ni = 0; ni < 4; ni++) {
        const int col = bn + wn * 32 + ni * 8 + tg * 2;
        pbv[ni][0] = g_pb[col];
        pbv[ni][1] = g_pb[col + 1];
    }
#pragma unroll
    for (int mi = 0; mi < 2; mi++) {
        const int r = bm + wm * 32 + mi * 16 + gid;
#pragma unroll
        for (int ni = 0; ni < 4; ni++) {
            const int col = bn + wn * 32 + ni * 8 + tg * 2;
            float2 c0 = *(const float2*)(g_cp + (size_t)r * OUT_DIM + col);
            float2 c1 = *(const float2*)(g_cp + (size_t)(r + 8) * OUT_DIM + col);
            float2 v0, v1;
            v0.x = tanhf(acc[mi][ni][0] + c0.x + pbv[ni][0]);
            v0.y = tanhf(acc[mi][ni][1] + c0.y + pbv[ni][1]);
            v1.x = tanhf(acc[mi][ni][2] + c1.x + pbv[ni][0]);
            v1.y = tanhf(acc[mi][ni][3] + c1.y + pbv[ni][1]);
            *(float2*)(out + (size_t)r * OUT_DIM + col)       = v0;
            *(float2*)(out + (size_t)(r + 8) * OUT_DIM + col) = v1;
        }
    }
}

// ---------------------------------------------------------------------------
// Host launch
// ---------------------------------------------------------------------------
extern "C" void kernel_launch(void* const* d_in, const int* in_sizes, int n_in,
                              void* d_out, int out_size) {
    const float *x = nullptr, *uw = nullptr, *cw = nullptr, *cb = nullptr;
    for (int i = 0; i < n_in; i++) {
        switch (in_sizes[i]) {
            case BATCH * IN_DIM:           x  = (const float*)d_in[i]; break;
            case DEPTH * IN_DIM * OUT_DIM: uw = (const float*)d_in[i]; break;
            case IN_DIM * OUT_DIM:         cw = (const float*)d_in[i]; break;
            case OUT_DIM:                  cb = (const float*)d_in[i]; break;
            default: break;
        }
    }
    float* out = (float*)d_out;

    static int attr_done = 0;
    if (!attr_done) {
        cudaFuncSetAttribute(gemm_i8_kernel,
                             cudaFuncAttributeMaxDynamicSharedMemorySize, I_SMEM);
        cudaFuncSetAttribute(gemm_hh_kernel,
                             cudaFuncAttributeMaxDynamicSharedMemorySize, H_SMEM);
        attr_done = 1;
    }

    prepA_kernel<<<16, 256>>>(cw, uw, cb);                       // colmax + probs
    prepX_kernel<<<BATCH, 256>>>(x);                             // per-row x split
    prepW_kernel<<<dim3(OUT_DIM / 32, IN_DIM / 32), 256>>>(cw);  // W split (needs colmax)

    dim3 grid(OUT_DIM / BN, BATCH / BM);   // (32, 64)
    gemm_i8_kernel<<<grid, 256, I_SMEM>>>();
    gemm_hh_kernel<<<grid, 256, H_SMEM>>>(out);
}

// round 14
// speedup vs baseline: 2.7558x; 2.7558x over previous
#include <cuda_runtime.h>
#include <cuda_bf16.h>
#include <math.h>
#include <stdint.h>

// ---------------------------------------------------------------------------
// Problem constants
// ---------------------------------------------------------------------------
#define BATCH   8192
#define IN_DIM  4096
#define OUT_DIM 2048
#define DEPTH   9
#define RSTEPS  27
#define WIN     55
#define CENTER  27

// GEMM tiling: 128x64 CTA tile, BK=64, 2-stage ring, 2 CTAs/SM  (R12 config)
#define BM 128
#define BN 64
#define BK 64
#define NKT (IN_DIM / BK)            // 64
#define STAGES 2
// Stage layout (128B rows): Ahi 16K | Alo 16K | Bhi 8K | Blo 8K
#define AHI 0
#define ALO 16384
#define BHI 32768
#define BLO 40960
#define STAGE_BYTES 49152
#define SMEM_TOTAL (STAGES * STAGE_BYTES)   // 98304/CTA -> 2 CTAs = 192KB/SM

// ---------------------------------------------------------------------------
// Device-global scratch (static: no runtime allocation)
// ---------------------------------------------------------------------------
__device__ float         g_pb[OUT_DIM];
__device__ __nv_bfloat16 g_xhi[(size_t)BATCH * IN_DIM];
__device__ __nv_bfloat16 g_xlo[(size_t)BATCH * IN_DIM];
__device__ __nv_bfloat16 g_wThi[(size_t)OUT_DIM * IN_DIM];   // W^T [N][K]
__device__ __nv_bfloat16 g_wTlo[(size_t)OUT_DIM * IN_DIM];

// ---------------------------------------------------------------------------
// PTX helpers (base sm_103 ISA only: cp.async / ldmatrix / mma.sync)
// ---------------------------------------------------------------------------
__device__ __forceinline__ uint32_t smem_u32(const void* p) {
    uint32_t a;
    asm("{ .reg .u64 t; cvta.to.shared.u64 t, %1; cvt.u32.u64 %0, t; }"
        : "=r"(a) : "l"(p));
    return a;
}
__device__ __forceinline__ void cpasync16(uint32_t dst, const void* src) {
    asm volatile("cp.async.cg.shared.global [%0], [%1], 16;"
                 :: "r"(dst), "l"(src));
}
#define CP_COMMIT() asm volatile("cp.async.commit_group;" ::: "memory")
#define CP_WAIT0()  asm volatile("cp.async.wait_group 0;"  ::: "memory")

#define LDSM_X4(d, a) \
    asm volatile("ldmatrix.sync.aligned.m8n8.x4.shared.b16 {%0,%1,%2,%3}, [%4];" \
        : "=r"((d)[0]), "=r"((d)[1]), "=r"((d)[2]), "=r"((d)[3]) : "r"(a))

#define MMA16816(c, a, b) \
    asm volatile("mma.sync.aligned.m16n8k16.row.col.f32.bf16.bf16.f32 " \
        "{%0,%1,%2,%3}, {%4,%5,%6,%7}, {%8,%9}, {%0,%1,%2,%3};" \
        : "+f"((c)[0]), "+f"((c)[1]), "+f"((c)[2]), "+f"((c)[3]) \
        : "r"((a)[0]), "r"((a)[1]), "r"((a)[2]), "r"((a)[3]), \
          "r"((b)[0]), "r"((b)[1]))

// SW128 swizzle for 128B physical rows: row r, 16B-chunk cc in 0..7.
__device__ __forceinline__ uint32_t swz128(uint32_t base, int row, int cc) {
    return base + row * 128 + (((cc) ^ (row & 7)) << 4);
}

// ---------------------------------------------------------------------------
// Fused prepass kernel: one launch, roles by blockIdx.x range.
//   [0, 16384)            split x -> (hi, lo) bf16   (8 elems/thread, 16B stores)
//   [16384, 24576)        transpose+split W -> wT hi/lo
//   [24576, 24584)        universal probs + bias -> g_pb
// ---------------------------------------------------------------------------
#define SPLITX_BLOCKS 16384   // (8192*4096)/(8*256)
#define SPLITW_BLOCKS 8192    // (2048/32)*(4096/32)
#define PROBS_BLOCKS  8
#define PREP_BLOCKS   (SPLITX_BLOCKS + SPLITW_BLOCKS + PROBS_BLOCKS)

__device__ __forceinline__ uint32_t split_pair(float a, float b, uint32_t* lo) {
    __nv_bfloat16 ha = __float2bfloat16(a);
    __nv_bfloat16 hb = __float2bfloat16(b);
    __nv_bfloat162 hp(ha, hb);
    __nv_bfloat162 lp(__float2bfloat16(a - __bfloat162float(ha)),
                      __float2bfloat16(b - __bfloat162float(hb)));
    *lo = *(uint32_t*)&lp;
    return *(uint32_t*)&hp;
}

__global__ __launch_bounds__(256)
void prep_kernel(const float* __restrict__ x,
                 const float* __restrict__ W,
                 const float* __restrict__ uw,
                 const float* __restrict__ bias) {
    __shared__ float t[32][33];
    const int b   = blockIdx.x;
    const int tid = threadIdx.x;

    if (b < SPLITX_BLOCKS) {
        // ---- split x: 8 elements/thread, 16B hi store + 16B lo store ----
        size_t i = ((size_t)b * 256 + tid) * 8;
        float4 v0 = *(const float4*)(x + i);
        float4 v1 = *(const float4*)(x + i + 4);
        uint4 hi, lo;
        hi.x = split_pair(v0.x, v0.y, &lo.x);
        hi.y = split_pair(v0.z, v0.w, &lo.y);
        hi.z = split_pair(v1.x, v1.y, &lo.z);
        hi.w = split_pair(v1.z, v1.w, &lo.w);
        *(uint4*)(g_xhi + i) = hi;
        *(uint4*)(g_xlo + i) = lo;
    } else if (b < SPLITX_BLOCKS + SPLITW_BLOCKS) {
        // ---- transpose + split W ----
        const int bw = b - SPLITX_BLOCKS;
        const int n0 = (bw & 63) * 32;
        const int k0 = (bw >> 6) * 32;
        const int tx = tid & 31, ty = tid >> 5;   // 32 x 8
#pragma unroll
        for (int i = 0; i < 32; i += 8)
            t[ty + i][tx] = W[(size_t)(k0 + ty + i) * OUT_DIM + n0 + tx];
        __syncthreads();
#pragma unroll
        for (int i = 0; i < 32; i += 8) {
            float v = t[tx][ty + i];
            __nv_bfloat16 h = __float2bfloat16(v);
            size_t o = (size_t)(n0 + ty + i) * IN_DIM + k0 + tx;
            g_wThi[o] = h;
            g_wTlo[o] = __float2bfloat16(v - __bfloat162float(h));
        }
    } else {
        // ---- universal probs (dependency-cone trick) ----
        const int o = (b - SPLITX_BLOCKS - SPLITW_BLOCKS) * 256 + tid;
        if (o >= OUT_DIM) return;
        float w[WIN];
#pragma unroll
        for (int j = 0; j < WIN; j++) w[j] = 0.015625f;   // 1/sqrt(4096)
#pragma unroll
        for (int s = 0; s < RSTEPS; s++) {
            const int d = s / 3, g = s % 3;
            float ang = uw[(size_t)d * IN_DIM * OUT_DIM + (size_t)o * OUT_DIM + g];
            float sn, cs;
            sincosf(ang, &sn, &cs);
            float nw[WIN];
            nw[0] = w[0]; nw[WIN - 1] = w[WIN - 1];
#pragma unroll
            for (int j = 1; j < WIN - 1; j++)
                nw[j] = cs * w[j] - sn * w[j + 1] + sn * w[j - 1];
#pragma unroll
            for (int j = 0; j < WIN; j++) w[j] = nw[j];
        }
        g_pb[o] = w[CENTER] * w[CENTER] + bias[o];
    }
}

// ---------------------------------------------------------------------------
// GEMM kernel: C = tanh(x @ W + g_pb) via bf16x3 mma.sync.  (R12 verbatim)
// 128x64x64 chunks, 2-stage ring, 2 CTAs/SM, 8 warps, warp tile 32x32.
// ONE wait0+__syncthreads per BK=64 chunk; no cross-stage reads; refill
// issued mid-iteration (~25% in) -> ~2300 cyc latency headroom.
// ---------------------------------------------------------------------------
__global__ __launch_bounds__(256, 2)
void gemm_bf16x3_kernel(float* __restrict__ out) {
    extern __shared__ char smem[];
    const uint32_t sb = smem_u32(smem);

    const int tid  = threadIdx.x;
    const int lane = tid & 31;
    const int wid  = tid >> 5;
    const int wm   = wid >> 1;          // 0..3  -> m offset wm*32
    const int wn   = wid & 1;           // 0..1  -> n offset wn*32
    const int gid  = lane >> 2;
    const int tg   = lane & 3;
    const int bm   = blockIdx.y * BM;
    const int bn   = blockIdx.x * BN;

    // --- global load mapping: 12 x 16B chunks per thread per BK=64 chunk ---
    const int r0 = tid >> 3;            // 0..31
    const int cA = tid & 7;             // 16B chunk in 128B row

    const __nv_bfloat16* pAh = g_xhi  + (size_t)(bm + r0) * IN_DIM + cA * 8;
    const __nv_bfloat16* pAl = g_xlo  + (size_t)(bm + r0) * IN_DIM + cA * 8;
    const __nv_bfloat16* pBh = g_wThi + (size_t)(bn + r0) * IN_DIM + cA * 8;
    const __nv_bfloat16* pBl = g_wTlo + (size_t)(bn + r0) * IN_DIM + cA * 8;

    const uint32_t dAh = swz128(AHI, r0, cA);
    const uint32_t dAl = swz128(ALO, r0, cA);
    const uint32_t dBh = swz128(BHI, r0, cA);
    const uint32_t dBl = swz128(BLO, r0, cA);

#define ISSUE_CHUNK(stg, kc)                                                 \
    do {                                                                     \
        uint32_t s_ = sb + (stg) * STAGE_BYTES;                              \
        size_t ko_ = (size_t)(kc) * BK;                                      \
        _Pragma("unroll")                                                    \
        for (int i = 0; i < 4; i++) {                                        \
            cpasync16(s_ + dAh + i * 4096, pAh + ko_ + (size_t)i * 32 * IN_DIM); \
            cpasync16(s_ + dAl + i * 4096, pAl + ko_ + (size_t)i * 32 * IN_DIM); \
        }                                                                    \
        _Pragma("unroll")                                                    \
        for (int i = 0; i < 2; i++) {                                        \
            cpasync16(s_ + dBh + i * 4096, pBh + ko_ + (size_t)i * 32 * IN_DIM); \
            cpasync16(s_ + dBl + i * 4096, pBl + ko_ + (size_t)i * 32 * IN_DIM); \
        }                                                                    \
    } while (0)

    float acc[2][4][4];
#pragma unroll
    for (int i = 0; i < 2; i++)
#pragma unroll
        for (int j = 0; j < 4; j++)
#pragma unroll
            for (int q = 0; q < 4; q++) acc[i][j][q] = 0.0f;

    // Per-lane ldmatrix logical coordinates (ks phase 0..3 -> cc = ks*2 + ch)
    const int a_rl = lane & 15;               // A: rows m0..m0+15
    const int a_ch = lane >> 4;               // A: +0 / +1 chunk
    const int b4_row = ((lane >> 4) << 3) + (lane & 7);   // B x4 ni-pair
    const int b4_c   = (lane >> 3) & 1;

    uint32_t oA[4][2], oB[4][2];              // [ks][mi] / [ks][nj]
#pragma unroll
    for (int ks = 0; ks < 4; ks++) {
#pragma unroll
        for (int mi = 0; mi < 2; mi++)
            oA[ks][mi] = swz128(0, wm * 32 + mi * 16 + a_rl, ks * 2 + a_ch);
#pragma unroll
        for (int nj = 0; nj < 2; nj++)
            oB[ks][nj] = swz128(0, wn * 32 + nj * 16 + b4_row, ks * 2 + b4_c);
    }

    // Fragment registers: hi double-buffered, lo just-in-time
    uint32_t ah0[2][4], ah1[2][4];
    uint32_t bh0[4][2], bh1[4][2];
    uint32_t al[2][4],  bl[4][2];

#define LOAD_HI(AH, BH, SBASE, KS)                                           \
    do {                                                                     \
        LDSM_X4(AH[0],     (SBASE) + AHI + oA[KS][0]);                       \
        LDSM_X4(AH[1],     (SBASE) + AHI + oA[KS][1]);                       \
        LDSM_X4(&BH[0][0], (SBASE) + BHI + oB[KS][0]);                       \
        LDSM_X4(&BH[2][0], (SBASE) + BHI + oB[KS][1]);                       \
    } while (0)

#define LOAD_LO(SBASE, KS)                                                   \
    do {                                                                     \
        LDSM_X4(al[0],     (SBASE) + ALO + oA[KS][0]);                       \
        LDSM_X4(al[1],     (SBASE) + ALO + oA[KS][1]);                       \
        LDSM_X4(&bl[0][0], (SBASE) + BLO + oB[KS][0]);                       \
        LDSM_X4(&bl[2][0], (SBASE) + BLO + oB[KS][1]);                       \
    } while (0)

#define MMA_PHASE(AH, BH)                                                    \
    do {                                                                     \
        _Pragma("unroll")                                                    \
        for (int mi = 0; mi < 2; mi++)                                       \
            _Pragma("unroll")                                                \
            for (int ni = 0; ni < 4; ni++)                                   \
                MMA16816(acc[mi][ni], AH[mi], BH[ni]);                       \
        _Pragma("unroll")                                                    \
        for (int mi = 0; mi < 2; mi++)                                       \
            _Pragma("unroll")                                                \
            for (int ni = 0; ni < 4; ni++)                                   \
                MMA16816(acc[mi][ni], AH[mi], bl[ni]);                       \
        _Pragma("unroll")                                                    \
        for (int mi = 0; mi < 2; mi++)                                       \
            _Pragma("unroll")                                                \
            for (int ni = 0; ni < 4; ni++)                                   \
                MMA16816(acc[mi][ni], al[mi], BH[ni]);                       \
    } while (0)

    // Prologue: chunk 0 -> stage 0
    ISSUE_CHUNK(0, 0);
    CP_COMMIT();

#pragma unroll 1
    for (int kt = 0; kt < NKT; kt++) {
        CP_WAIT0();
        __syncthreads();

        const uint32_t s_cur = sb + (kt & 1) * STAGE_BYTES;

        // phase 0 hi (only exposed LDSM of the chunk; other CTA covers)
        LOAD_HI(ah0, bh0, s_cur, 0);

        // ---- phase 0 ----
        LOAD_LO(s_cur, 0);
        LOAD_HI(ah1, bh1, s_cur, 1);
        MMA_PHASE(ah0, bh0);

        // Refill: chunk kt+1 -> other stage (consumed at kt-1; top barrier
        // of this iteration protects it; no reads of that stage here).
        if (kt + 1 < NKT) {
            ISSUE_CHUNK((kt + 1) & 1, kt + 1);
            CP_COMMIT();
        }

        // ---- phase 1 ----
        LOAD_LO(s_cur, 1);
        LOAD_HI(ah0, bh0, s_cur, 2);
        MMA_PHASE(ah1, bh1);

        // ---- phase 2 ----
        LOAD_LO(s_cur, 2);
        LOAD_HI(ah1, bh1, s_cur, 3);
        MMA_PHASE(ah0, bh0);

        // ---- phase 3 ----
        LOAD_LO(s_cur, 3);
        MMA_PHASE(ah1, bh1);
    }

    // ------------------- epilogue: +pb, tanh, store -------------------
    float pbv[4][2];
#pragma unroll
    for (int ni = 0; ni < 4; ni++) {
        const int col = bn + wn * 32 + ni * 8 + tg * 2;
        pbv[ni][0] = g_pb[col];
        pbv[ni][1] = g_pb[col + 1];
    }
#pragma unroll
    for (int mi = 0; mi < 2; mi++) {
        const int r = bm + wm * 32 + mi * 16 + gid;
#pragma unroll
        for (int ni = 0; ni < 4; ni++) {
            const int col = bn + wn * 32 + ni * 8 + tg * 2;
            float2 v0, v1;
            v0.x = tanhf(acc[mi][ni][0] + pbv[ni][0]);
            v0.y = tanhf(acc[mi][ni][1] + pbv[ni][1]);
            v1.x = tanhf(acc[mi][ni][2] + pbv[ni][0]);
            v1.y = tanhf(acc[mi][ni][3] + pbv[ni][1]);
            *(float2*)(out + (size_t)r * OUT_DIM + col)       = v0;
            *(float2*)(out + (size_t)(r + 8) * OUT_DIM + col) = v1;
        }
    }
}

// ---------------------------------------------------------------------------
// Host launch
// ---------------------------------------------------------------------------
extern "C" void kernel_launch(void* const* d_in, const int* in_sizes, int n_in,
                              void* d_out, int out_size) {
    const float *x = nullptr, *uw = nullptr, *cw = nullptr, *cb = nullptr;
    for (int i = 0; i < n_in; i++) {
        switch (in_sizes[i]) {
            case BATCH * IN_DIM:           x  = (const float*)d_in[i]; break;
            case DEPTH * IN_DIM * OUT_DIM: uw = (const float*)d_in[i]; break;
            case IN_DIM * OUT_DIM:         cw = (const float*)d_in[i]; break;
            case OUT_DIM:                  cb = (const float*)d_in[i]; break;
            default: break;
        }
    }
    float* out = (float*)d_out;

    prep_kernel<<<PREP_BLOCKS, 256>>>(x, cw, uw, cb);

    static int attr_done = 0;
    if (!attr_done) {
        cudaFuncSetAttribute(gemm_bf16x3_kernel,
                             cudaFuncAttributeMaxDynamicSharedMemorySize,
                             SMEM_TOTAL);
        attr_done = 1;
    }
    dim3 grid(OUT_DIM / BN, BATCH / BM);   // (32, 64)
    gemm_bf16x3_kernel<<<grid, 256, SMEM_TOTAL>>>(out);
}

// round 15
// speedup vs baseline: 2.7800x; 1.0088x over previous
#include <cuda_runtime.h>
#include <cuda_bf16.h>
#include <math.h>
#include <stdint.h>

// ---------------------------------------------------------------------------
// Problem constants
// ---------------------------------------------------------------------------
#define BATCH   8192
#define IN_DIM  4096
#define OUT_DIM 2048
#define DEPTH   9
#define RSTEPS  27
#define WIN     55
#define CENTER  27

// GEMM tiling: 128x64 CTA tile, BK=64, 2-stage ring, 2 CTAs/SM  (R12 config)
#define BM 128
#define BN 64
#define BK 64
#define NKT (IN_DIM / BK)            // 64
#define STAGES 2
// Stage layout (128B rows): Ahi 16K | Alo 16K | Bhi 8K | Blo 8K
#define AHI 0
#define ALO 16384
#define BHI 32768
#define BLO 40960
#define STAGE_BYTES 49152
#define SMEM_TOTAL (STAGES * STAGE_BYTES)   // 98304/CTA -> 2 CTAs = 192KB/SM

// ---------------------------------------------------------------------------
// Device-global scratch (static: no runtime allocation)
// ---------------------------------------------------------------------------
__device__ float         g_pb[OUT_DIM];
__device__ __nv_bfloat16 g_xhi[(size_t)BATCH * IN_DIM];
__device__ __nv_bfloat16 g_xlo[(size_t)BATCH * IN_DIM];
__device__ __nv_bfloat16 g_wThi[(size_t)OUT_DIM * IN_DIM];   // W^T [N][K]
__device__ __nv_bfloat16 g_wTlo[(size_t)OUT_DIM * IN_DIM];

// ---------------------------------------------------------------------------
// PTX helpers (base sm_103 ISA only: cp.async / ldmatrix / mma.sync)
// ---------------------------------------------------------------------------
__device__ __forceinline__ uint32_t smem_u32(const void* p) {
    uint32_t a;
    asm("{ .reg .u64 t; cvta.to.shared.u64 t, %1; cvt.u32.u64 %0, t; }"
        : "=r"(a) : "l"(p));
    return a;
}
__device__ __forceinline__ void cpasync16(uint32_t dst, const void* src) {
    asm volatile("cp.async.cg.shared.global [%0], [%1], 16;"
                 :: "r"(dst), "l"(src));
}
#define CP_COMMIT() asm volatile("cp.async.commit_group;" ::: "memory")
#define CP_WAIT0()  asm volatile("cp.async.wait_group 0;"  ::: "memory")

#define LDSM_X4(d, a) \
    asm volatile("ldmatrix.sync.aligned.m8n8.x4.shared.b16 {%0,%1,%2,%3}, [%4];" \
        : "=r"((d)[0]), "=r"((d)[1]), "=r"((d)[2]), "=r"((d)[3]) : "r"(a))

#define MMA16816(c, a, b) \
    asm volatile("mma.sync.aligned.m16n8k16.row.col.f32.bf16.bf16.f32 " \
        "{%0,%1,%2,%3}, {%4,%5,%6,%7}, {%8,%9}, {%0,%1,%2,%3};" \
        : "+f"((c)[0]), "+f"((c)[1]), "+f"((c)[2]), "+f"((c)[3]) \
        : "r"((a)[0]), "r"((a)[1]), "r"((a)[2]), "r"((a)[3]), \
          "r"((b)[0]), "r"((b)[1]))

// SW128 swizzle for 128B physical rows: row r, 16B-chunk cc in 0..7.
__device__ __forceinline__ uint32_t swz128(uint32_t base, int row, int cc) {
    return base + row * 128 + (((cc) ^ (row & 7)) << 4);
}

// ---------------------------------------------------------------------------
// Fused prepass kernel: one launch, roles by blockIdx.x range.
//   [0, 16384)            split x -> (hi, lo) bf16   (8 elems/thread, 16B stores)
//   [16384, 24576)        transpose+split W -> wT hi/lo (4-wide 8B stores)
//   [24576, 24584)        universal probs + bias -> g_pb
// ---------------------------------------------------------------------------
#define SPLITX_BLOCKS 16384   // (8192*4096)/(8*256)
#define SPLITW_BLOCKS 8192    // (2048/32)*(4096/32)
#define PROBS_BLOCKS  8
#define PREP_BLOCKS   (SPLITX_BLOCKS + SPLITW_BLOCKS + PROBS_BLOCKS)

__device__ __forceinline__ uint32_t split_pair(float a, float b, uint32_t* lo) {
    __nv_bfloat16 ha = __float2bfloat16(a);
    __nv_bfloat16 hb = __float2bfloat16(b);
    __nv_bfloat162 hp(ha, hb);
    __nv_bfloat162 lp(__float2bfloat16(a - __bfloat162float(ha)),
                      __float2bfloat16(b - __bfloat162float(hb)));
    *lo = *(uint32_t*)&lp;
    return *(uint32_t*)&hp;
}

__global__ __launch_bounds__(256)
void prep_kernel(const float* __restrict__ x,
                 const float* __restrict__ W,
                 const float* __restrict__ uw,
                 const float* __restrict__ bias) {
    __shared__ float t[32][33];
    const int b   = blockIdx.x;
    const int tid = threadIdx.x;

    if (b < SPLITX_BLOCKS) {
        // ---- split x: 8 elements/thread, 16B hi store + 16B lo store ----
        size_t i = ((size_t)b * 256 + tid) * 8;
        float4 v0 = *(const float4*)(x + i);
        float4 v1 = *(const float4*)(x + i + 4);
        uint4 hi, lo;
        hi.x = split_pair(v0.x, v0.y, &lo.x);
        hi.y = split_pair(v0.z, v0.w, &lo.y);
        hi.z = split_pair(v1.x, v1.y, &lo.z);
        hi.w = split_pair(v1.z, v1.w, &lo.w);
        *(uint4*)(g_xhi + i) = hi;
        *(uint4*)(g_xlo + i) = lo;
    } else if (b < SPLITX_BLOCKS + SPLITW_BLOCKS) {
        // ---- transpose + split W (vectorized output: 4 k per thread) ----
        const int bw = b - SPLITX_BLOCKS;
        const int n0 = (bw & 63) * 32;
        const int k0 = (bw >> 6) * 32;
        const int tx = tid & 31, ty = tid >> 5;   // 32 x 8 load mapping
#pragma unroll
        for (int i = 0; i < 32; i += 8)
            t[ty + i][tx] = W[(size_t)(k0 + ty + i) * OUT_DIM + n0 + tx];
        __syncthreads();
        // Store mapping: thread = (row n = tid&31, k-quad q = tid>>5)
        const int n = tid & 31;
        const int q = (tid >> 5) * 4;             // k offset 0,4,...,28
        uint32_t h2[2], l2[2];
#pragma unroll
        for (int j = 0; j < 2; j++) {
            float a = t[q + j * 2][n];
            float c = t[q + j * 2 + 1][n];
            h2[j] = split_pair(a, c, &l2[j]);
        }
        size_t o = (size_t)(n0 + n) * IN_DIM + k0 + q;
        *(uint2*)(g_wThi + o) = make_uint2(h2[0], h2[1]);
        *(uint2*)(g_wTlo + o) = make_uint2(l2[0], l2[1]);
    } else {
        // ---- universal probs (dependency-cone trick) ----
        const int o = (b - SPLITX_BLOCKS - SPLITW_BLOCKS) * 256 + tid;
        if (o >= OUT_DIM) return;
        float w[WIN];
#pragma unroll
        for (int j = 0; j < WIN; j++) w[j] = 0.015625f;   // 1/sqrt(4096)
#pragma unroll
        for (int s = 0; s < RSTEPS; s++) {
            const int d = s / 3, g = s % 3;
            float ang = uw[(size_t)d * IN_DIM * OUT_DIM + (size_t)o * OUT_DIM + g];
            float sn, cs;
            sincosf(ang, &sn, &cs);
            float nw[WIN];
            nw[0] = w[0]; nw[WIN - 1] = w[WIN - 1];
#pragma unroll
            for (int j = 1; j < WIN - 1; j++)
                nw[j] = cs * w[j] - sn * w[j + 1] + sn * w[j - 1];
#pragma unroll
            for (int j = 0; j < WIN; j++) w[j] = nw[j];
        }
        g_pb[o] = w[CENTER] * w[CENTER] + bias[o];
    }
}

// ---------------------------------------------------------------------------
// GEMM kernel: C = tanh(x @ W + g_pb) via bf16x3 mma.sync.  (R12/R14 core)
// 128x64x64 chunks, 2-stage ring, 2 CTAs/SM, 8 warps, warp tile 32x32.
// ONE wait0+__syncthreads per BK=64 chunk; no cross-stage reads; refill
// split into A-half (after phase 0) and B-half (after phase 1) with a
// single commit -> smoother LSU cadence, same group accounting.
// ---------------------------------------------------------------------------
__global__ __launch_bounds__(256, 2)
void gemm_bf16x3_kernel(float* __restrict__ out) {
    extern __shared__ char smem[];
    const uint32_t sb = smem_u32(smem);

    const int tid  = threadIdx.x;
    const int lane = tid & 31;
    const int wid  = tid >> 5;
    const int wm   = wid >> 1;          // 0..3  -> m offset wm*32
    const int wn   = wid & 1;           // 0..1  -> n offset wn*32
    const int gid  = lane >> 2;
    const int tg   = lane & 3;
    const int bm   = blockIdx.y * BM;
    const int bn   = blockIdx.x * BN;

    // --- global load mapping: 12 x 16B chunks per thread per BK=64 chunk ---
    const int r0 = tid >> 3;            // 0..31
    const int cA = tid & 7;             // 16B chunk in 128B row

    const __nv_bfloat16* pAh = g_xhi  + (size_t)(bm + r0) * IN_DIM + cA * 8;
    const __nv_bfloat16* pAl = g_xlo  + (size_t)(bm + r0) * IN_DIM + cA * 8;
    const __nv_bfloat16* pBh = g_wThi + (size_t)(bn + r0) * IN_DIM + cA * 8;
    const __nv_bfloat16* pBl = g_wTlo + (size_t)(bn + r0) * IN_DIM + cA * 8;

    const uint32_t dAh = swz128(AHI, r0, cA);
    const uint32_t dAl = swz128(ALO, r0, cA);
    const uint32_t dBh = swz128(BHI, r0, cA);
    const uint32_t dBl = swz128(BLO, r0, cA);

#define ISSUE_A(stg, kc)                                                     \
    do {                                                                     \
        uint32_t s_ = sb + (stg) * STAGE_BYTES;                              \
        size_t ko_ = (size_t)(kc) * BK;                                      \
        _Pragma("unroll")                                                    \
        for (int i = 0; i < 4; i++) {                                        \
            cpasync16(s_ + dAh + i * 4096, pAh + ko_ + (size_t)i * 32 * IN_DIM); \
            cpasync16(s_ + dAl + i * 4096, pAl + ko_ + (size_t)i * 32 * IN_DIM); \
        }                                                                    \
    } while (0)

#define ISSUE_B(stg, kc)                                                     \
    do {                                                                     \
        uint32_t s_ = sb + (stg) * STAGE_BYTES;                              \
        size_t ko_ = (size_t)(kc) * BK;                                      \
        _Pragma("unroll")                                                    \
        for (int i = 0; i < 2; i++) {                                        \
            cpasync16(s_ + dBh + i * 4096, pBh + ko_ + (size_t)i * 32 * IN_DIM); \
            cpasync16(s_ + dBl + i * 4096, pBl + ko_ + (size_t)i * 32 * IN_DIM); \
        }                                                                    \
    } while (0)

    float acc[2][4][4];
#pragma unroll
    for (int i = 0; i < 2; i++)
#pragma unroll
        for (int j = 0; j < 4; j++)
#pragma unroll
            for (int q = 0; q < 4; q++) acc[i][j][q] = 0.0f;

    // Per-lane ldmatrix logical coordinates (ks phase 0..3 -> cc = ks*2 + ch)
    const int a_rl = lane & 15;               // A: rows m0..m0+15
    const int a_ch = lane >> 4;               // A: +0 / +1 chunk
    const int b4_row = ((lane >> 4) << 3) + (lane & 7);   // B x4 ni-pair
    const int b4_c   = (lane >> 3) & 1;

    uint32_t oA[4][2], oB[4][2];              // [ks][mi] / [ks][nj]
#pragma unroll
    for (int ks = 0; ks < 4; ks++) {
#pragma unroll
        for (int mi = 0; mi < 2; mi++)
            oA[ks][mi] = swz128(0, wm * 32 + mi * 16 + a_rl, ks * 2 + a_ch);
#pragma unroll
        for (int nj = 0; nj < 2; nj++)
            oB[ks][nj] = swz128(0, wn * 32 + nj * 16 + b4_row, ks * 2 + b4_c);
    }

    // Fragment registers: hi double-buffered, lo just-in-time
    uint32_t ah0[2][4], ah1[2][4];
    uint32_t bh0[4][2], bh1[4][2];
    uint32_t al[2][4],  bl[4][2];

#define LOAD_HI(AH, BH, SBASE, KS)                                           \
    do {                                                                     \
        LDSM_X4(AH[0],     (SBASE) + AHI + oA[KS][0]);                       \
        LDSM_X4(AH[1],     (SBASE) + AHI + oA[KS][1]);                       \
        LDSM_X4(&BH[0][0], (SBASE) + BHI + oB[KS][0]);                       \
        LDSM_X4(&BH[2][0], (SBASE) + BHI + oB[KS][1]);                       \
    } while (0)

#define LOAD_LO(SBASE, KS)                                                   \
    do {                                                                     \
        LDSM_X4(al[0],     (SBASE) + ALO + oA[KS][0]);                       \
        LDSM_X4(al[1],     (SBASE) + ALO + oA[KS][1]);                       \
        LDSM_X4(&bl[0][0], (SBASE) + BLO + oB[KS][0]);                       \
        LDSM_X4(&bl[2][0], (SBASE) + BLO + oB[KS][1]);                       \
    } while (0)

#define MMA_PHASE(AH, BH)                                                    \
    do {                                                                     \
        _Pragma("unroll")                                                    \
        for (int mi = 0; mi < 2; mi++)                                       \
            _Pragma("unroll")                                                \
            for (int ni = 0; ni < 4; ni++)                                   \
                MMA16816(acc[mi][ni], AH[mi], BH[ni]);                       \
        _Pragma("unroll")                                                    \
        for (int mi = 0; mi < 2; mi++)                                       \
            _Pragma("unroll")                                                \
            for (int ni = 0; ni < 4; ni++)                                   \
                MMA16816(acc[mi][ni], AH[mi], bl[ni]);                       \
        _Pragma("unroll")                                                    \
        for (int mi = 0; mi < 2; mi++)                                       \
            _Pragma("unroll")                                                \
            for (int ni = 0; ni < 4; ni++)                                   \
                MMA16816(acc[mi][ni], al[mi], BH[ni]);                       \
    } while (0)

    // Prologue: chunk 0 -> stage 0
    ISSUE_A(0, 0);
    ISSUE_B(0, 0);
    CP_COMMIT();

#pragma unroll 1
    for (int kt = 0; kt < NKT; kt++) {
        CP_WAIT0();
        __syncthreads();

        const uint32_t s_cur = sb + (kt & 1) * STAGE_BYTES;

        // phase 0 hi (only exposed LDSM of the chunk; other CTA covers)
        LOAD_HI(ah0, bh0, s_cur, 0);

        // ---- phase 0 ----
        LOAD_LO(s_cur, 0);
        LOAD_HI(ah1, bh1, s_cur, 1);
        MMA_PHASE(ah0, bh0);

        // Refill A-half: chunk kt+1 -> other stage (consumed at kt-1; the
        // top barrier of this iteration protects it).
        if (kt + 1 < NKT) {
            ISSUE_A((kt + 1) & 1, kt + 1);
        }

        // ---- phase 1 ----
        LOAD_LO(s_cur, 1);
        LOAD_HI(ah0, bh0, s_cur, 2);
        MMA_PHASE(ah1, bh1);

        // Refill B-half + single commit (group accounting unchanged:
        // one commit per chunk; wait0 at next top covers both halves).
        if (kt + 1 < NKT) {
            ISSUE_B((kt + 1) & 1, kt + 1);
            CP_COMMIT();
        }

        // ---- phase 2 ----
        LOAD_LO(s_cur, 2);
        LOAD_HI(ah1, bh1, s_cur, 3);
        MMA_PHASE(ah0, bh0);

        // ---- phase 3 ----
        LOAD_LO(s_cur, 3);
        MMA_PHASE(ah1, bh1);
    }

    // ------------------- epilogue: +pb, tanh, store -------------------
    float pbv[4][2];
#pragma unroll
    for (int ni = 0; ni < 4; ni++) {
        const int col = bn + wn * 32 + ni * 8 + tg * 2;
        pbv[ni][0] = g_pb[col];
        pbv[ni][1] = g_pb[col + 1];
    }
#pragma unroll
    for (int mi = 0; mi < 2; mi++) {
        const int r = bm + wm * 32 + mi * 16 + gid;
#pragma unroll
        for (int ni = 0; ni < 4; ni++) {
            const int col = bn + wn * 32 + ni * 8 + tg * 2;
            float2 v0, v1;
            v0.x = tanhf(acc[mi][ni][0] + pbv[ni][0]);
            v0.y = tanhf(acc[mi][ni][1] + pbv[ni][1]);
            v1.x = tanhf(acc[mi][ni][2] + pbv[ni][0]);
            v1.y = tanhf(acc[mi][ni][3] + pbv[ni][1]);
            *(float2*)(out + (size_t)r * OUT_DIM + col)       = v0;
            *(float2*)(out + (size_t)(r + 8) * OUT_DIM + col) = v1;
        }
    }
}

// ---------------------------------------------------------------------------
// Host launch
// ---------------------------------------------------------------------------
extern "C" void kernel_launch(void* const* d_in, const int* in_sizes, int n_in,
                              void* d_out, int out_size) {
    const float *x = nullptr, *uw = nullptr, *cw = nullptr, *cb = nullptr;
    for (int i = 0; i < n_in; i++) {
        switch (in_sizes[i]) {
            case BATCH * IN_DIM:           x  = (const float*)d_in[i]; break;
            case DEPTH * IN_DIM * OUT_DIM: uw = (const float*)d_in[i]; break;
            case IN_DIM * OUT_DIM:         cw = (const float*)d_in[i]; break;
            case OUT_DIM:                  cb = (const float*)d_in[i]; break;
            default: break;
        }
    }
    float* out = (float*)d_out;

    prep_kernel<<<PREP_BLOCKS, 256>>>(x, cw, uw, cb);

    static int attr_done = 0;
    if (!attr_done) {
        cudaFuncSetAttribute(gemm_bf16x3_kernel,
                             cudaFuncAttributeMaxDynamicSharedMemorySize,
                             SMEM_TOTAL);
        attr_done = 1;
    }
    dim3 grid(OUT_DIM / BN, BATCH / BM);   // (32, 64)
    gemm_bf16x3_kernel<<<grid, 256, SMEM_TOTAL>>>(out);
}